// round 1
// baseline (speedup 1.0000x reference)
#include <cuda_runtime.h>

#define T_      16384
#define CHUNK   256
#define WARM    256
#define NCH     (T_ / CHUNK)

// One EMA step for all three series. Updates carried state (es, el, sig),
// emits macd (m), signal (g), hist (h).
#define STEP(xv, m, g, h) do {                   \
    es  = fmaf(b_s, es, a_s * (xv));             \
    el  = fmaf(b_l, el, a_l * (xv));             \
    (m) = es - el;                               \
    sig = fmaf(b_g, sig, a_g * (m));             \
    (g) = sig;                                   \
    (h) = (m) - sig;                             \
} while (0)

// Warmup-only step: advance state, no outputs.
#define STEPW(xv) do {                           \
    es  = fmaf(b_s, es, a_s * (xv));             \
    el  = fmaf(b_l, el, a_l * (xv));             \
    float _m = es - el;                          \
    sig = fmaf(b_g, sig, a_g * _m);              \
} while (0)

__global__ __launch_bounds__(256)
void macd_chunked_kernel(const float* __restrict__ x,
                         const int*   __restrict__ p_short,
                         const int*   __restrict__ p_long,
                         const int*   __restrict__ p_sig,
                         float* __restrict__ out_macd,
                         float* __restrict__ out_sig,
                         float* __restrict__ out_hist,
                         int B)
{
    const int tid = blockIdx.x * blockDim.x + threadIdx.x;
    const int row = tid / NCH;
    const int ch  = tid - row * NCH;
    if (row >= B) return;

    const float a_s = 2.0f / (float)(p_short[0] + 1);
    const float a_l = 2.0f / (float)(p_long[0]  + 1);
    const float a_g = 2.0f / (float)(p_sig[0]   + 1);
    const float b_s = 1.0f - a_s;
    const float b_l = 1.0f - a_l;
    const float b_g = 1.0f - a_g;

    const float* xr   = x + (size_t)row * T_;
    const int    start = ch * CHUNK;

    float es, el, sig;

    // ---- Warmup: self-start WARM elements before the chunk (ch > 0). ----
    if (ch != 0) {
        int wt = start - WARM;
        float4 v = *(const float4*)(xr + wt);
        es = v.x; el = v.x; sig = 0.0f;       // pretend t=0 at warmup start
        STEPW(v.y); STEPW(v.z); STEPW(v.w);
        #pragma unroll 4
        for (wt += 4; wt < start; wt += 4) {
            float4 u = *(const float4*)(xr + wt);
            STEPW(u.x); STEPW(u.y); STEPW(u.z); STEPW(u.w);
        }
    }

    const size_t base = (size_t)row * T_ + start;
    float* __restrict__ om = out_macd + base;
    float* __restrict__ og = out_sig  + base;
    float* __restrict__ oh = out_hist + base;
    const float4* __restrict__ px = (const float4*)(xr + start);

    int i0 = 0;
    if (ch == 0) {
        // Exact reference init: y_0 = x_0 for both EMAs, signal_0 = macd_0 = 0.
        float4 v = px[0];
        es = v.x; el = v.x; sig = 0.0f;
        float m1, m2, m3, g1, g2, g3, h1, h2, h3;
        STEP(v.y, m1, g1, h1);
        STEP(v.z, m2, g2, h2);
        STEP(v.w, m3, g3, h3);
        ((float4*)om)[0] = make_float4(0.0f, m1, m2, m3);
        ((float4*)og)[0] = make_float4(0.0f, g1, g2, g3);
        ((float4*)oh)[0] = make_float4(0.0f, h1, h2, h3);
        i0 = 1;
    }

    #pragma unroll 4
    for (int i = i0; i < CHUNK / 4; ++i) {
        float4 v = px[i];
        float m0, m1, m2, m3, g0, g1, g2, g3, h0, h1, h2, h3;
        STEP(v.x, m0, g0, h0);
        STEP(v.y, m1, g1, h1);
        STEP(v.z, m2, g2, h2);
        STEP(v.w, m3, g3, h3);
        ((float4*)om)[i] = make_float4(m0, m1, m2, m3);
        ((float4*)og)[i] = make_float4(g0, g1, g2, g3);
        ((float4*)oh)[i] = make_float4(h0, h1, h2, h3);
    }
}

extern "C" void kernel_launch(void* const* d_in, const int* in_sizes, int n_in,
                              void* d_out, int out_size)
{
    const float* x       = (const float*)d_in[0];
    const int*   p_short = (const int*)d_in[1];
    const int*   p_long  = (const int*)d_in[2];
    const int*   p_sig   = (const int*)d_in[3];

    const int B = in_sizes[0] / T_;
    float* out = (float*)d_out;
    const size_t N = (size_t)B * T_;

    const int total   = B * NCH;
    const int threads = 256;
    const int blocks  = (total + threads - 1) / threads;

    macd_chunked_kernel<<<blocks, threads>>>(
        x, p_short, p_long, p_sig,
        out, out + N, out + 2 * N, B);
}